// round 1
// baseline (speedup 1.0000x reference)
#include <cuda_runtime.h>

// ---------------------------------------------------------------------------
// CrossNetLayer: h = x @ W_enc + b_enc ; then 4 cross layers:
//   s = x_l . w_l (per row), x_l = x_l + x0 * s + b_l
// B = D = H = 1024, DEPTH = 4, all fp32.
// Inputs (metadata order): x[1024*1024], W_enc[1024*1024], b_enc[1024],
//                          ws[4*1024], bs[4*1024]. Output: [1024*1024] fp32.
// ---------------------------------------------------------------------------

#define MSIZE 1024
#define NSIZE 1024
#define KSIZE 1024
#define DEPTH 4

// Scratch for the encoder output h (no cudaMalloc allowed).
__device__ float g_h[MSIZE * NSIZE];

// ---------------------------------------------------------------------------
// Kernel 1: SGEMM with fused bias.  C[m,n] = sum_k A[m,k]*B[k,n] + bias[n]
// Tiling: BM=64, BN=128, BK=16, 256 threads, per-thread 4x8 microtile.
// Grid: (N/BN, M/BM) = (8, 16) = 128 blocks (~1 wave on 148 SMs).
// ---------------------------------------------------------------------------
#define BM 64
#define BN 128
#define BK 16
#define TM 4
#define TN 8

__global__ __launch_bounds__(256, 1) void gemm_bias_kernel(
    const float* __restrict__ A,      // (M, K) row-major
    const float* __restrict__ B,      // (K, N) row-major
    const float* __restrict__ bias)   // (N)
{
    __shared__ float As[BK][BM];   // transposed A tile: As[k][m]
    __shared__ float Bs[BK][BN];

    const int tid = threadIdx.x;
    const int bn  = blockIdx.x;    // N tile
    const int bm  = blockIdx.y;    // M tile

    const float* Ab = A + (size_t)bm * BM * KSIZE;
    const float* Bb = B + (size_t)bn * BN;

    // A tile load mapping: 64 rows x 16 k, one float4 per thread along K
    const int aRow = tid >> 2;          // 0..63
    const int aCol = (tid & 3) << 2;    // 0,4,8,12
    // B tile load mapping: 16 k x 128 n, two float4 per thread along N
    const int bRow = tid >> 5;          // 0..7 (and +8)
    const int bCol = (tid & 31) << 2;   // 0..124

    // microtile mapping: 16 thread-rows x 16 thread-cols
    const int trow = tid >> 4;          // 0..15 -> M offset trow*TM
    const int tcol = tid & 15;          // 0..15 -> N offset tcol*TN

    float acc[TM][TN];
#pragma unroll
    for (int i = 0; i < TM; i++)
#pragma unroll
        for (int j = 0; j < TN; j++) acc[i][j] = 0.0f;

    for (int k0 = 0; k0 < KSIZE; k0 += BK) {
        // load A tile (coalesced along K), store transposed
        float4 a = *(const float4*)(Ab + (size_t)aRow * KSIZE + k0 + aCol);
        As[aCol + 0][aRow] = a.x;
        As[aCol + 1][aRow] = a.y;
        As[aCol + 2][aRow] = a.z;
        As[aCol + 3][aRow] = a.w;
        // load B tile (coalesced along N)
        float4 b0 = *(const float4*)(Bb + (size_t)(k0 + bRow) * NSIZE + bCol);
        *(float4*)&Bs[bRow][bCol] = b0;
        float4 b1 = *(const float4*)(Bb + (size_t)(k0 + bRow + 8) * NSIZE + bCol);
        *(float4*)&Bs[bRow + 8][bCol] = b1;
        __syncthreads();

#pragma unroll
        for (int k = 0; k < BK; k++) {
            float4 ar  = *(const float4*)&As[k][trow * TM];
            float4 br0 = *(const float4*)&Bs[k][tcol * TN];
            float4 br1 = *(const float4*)&Bs[k][tcol * TN + 4];
            float am[TM] = {ar.x, ar.y, ar.z, ar.w};
            float bn8[TN] = {br0.x, br0.y, br0.z, br0.w,
                             br1.x, br1.y, br1.z, br1.w};
#pragma unroll
            for (int i = 0; i < TM; i++)
#pragma unroll
                for (int j = 0; j < TN; j++)
                    acc[i][j] = fmaf(am[i], bn8[j], acc[i][j]);
        }
        __syncthreads();
    }

    // epilogue: add bias, write to g_h
#pragma unroll
    for (int i = 0; i < TM; i++) {
        const int r = bm * BM + trow * TM + i;
#pragma unroll
        for (int j = 0; j < TN; j += 4) {
            const int c = bn * BN + tcol * TN + j;
            float4 bv = *(const float4*)(bias + c);
            float4 v;
            v.x = acc[i][j + 0] + bv.x;
            v.y = acc[i][j + 1] + bv.y;
            v.z = acc[i][j + 2] + bv.z;
            v.w = acc[i][j + 3] + bv.w;
            *(float4*)(g_h + (size_t)r * NSIZE + c) = v;
        }
    }
}

// ---------------------------------------------------------------------------
// Kernel 2: fused CrossNet (all DEPTH layers), one block per row.
// 256 threads, each owns 4 contiguous elements (float4).
// ---------------------------------------------------------------------------
__global__ __launch_bounds__(256, 1) void cross_kernel(
    const float* __restrict__ ws,   // (DEPTH, H)
    const float* __restrict__ bs,   // (DEPTH, H)
    float* __restrict__ out)        // (B, H)
{
    const int H = NSIZE;
    const int row = blockIdx.x;
    const int t = threadIdx.x;

    __shared__ float red[8];
    __shared__ float s_bcast;

    float4 x0 = *(const float4*)(g_h + (size_t)row * H + t * 4);
    float4 xl = x0;

#pragma unroll
    for (int l = 0; l < DEPTH; l++) {
        float4 w = *(const float4*)(ws + l * H + t * 4);
        float part = xl.x * w.x + xl.y * w.y + xl.z * w.z + xl.w * w.w;
#pragma unroll
        for (int o = 16; o > 0; o >>= 1)
            part += __shfl_xor_sync(0xffffffffu, part, o);
        if ((t & 31) == 0) red[t >> 5] = part;
        __syncthreads();
        if (t == 0) {
            float s2 = 0.0f;
#pragma unroll
            for (int i = 0; i < 8; i++) s2 += red[i];
            s_bcast = s2;
        }
        __syncthreads();
        const float s = s_bcast;
        float4 b = *(const float4*)(bs + l * H + t * 4);
        xl.x = fmaf(x0.x, s, xl.x) + b.x;
        xl.y = fmaf(x0.y, s, xl.y) + b.y;
        xl.z = fmaf(x0.z, s, xl.z) + b.z;
        xl.w = fmaf(x0.w, s, xl.w) + b.w;
    }

    *(float4*)(out + (size_t)row * H + t * 4) = xl;
}

// ---------------------------------------------------------------------------
extern "C" void kernel_launch(void* const* d_in, const int* in_sizes, int n_in,
                              void* d_out, int out_size)
{
    const float* x     = (const float*)d_in[0];
    const float* W_enc = (const float*)d_in[1];
    const float* b_enc = (const float*)d_in[2];
    const float* ws    = (const float*)d_in[3];
    const float* bs    = (const float*)d_in[4];
    float* out = (float*)d_out;

    dim3 grid(NSIZE / BN, MSIZE / BM);   // (8, 16)
    gemm_bias_kernel<<<grid, 256>>>(x, W_enc, b_enc);
    cross_kernel<<<MSIZE, 256>>>(ws, bs, out);
}

// round 3
// speedup vs baseline: 3.2141x; 3.2141x over previous
#include <cuda_runtime.h>
#include <cuda_bf16.h>
#include <cstdint>

// ---------------------------------------------------------------------------
// CrossNetLayer on GB300 (sm_103a, but PTX target is compute_103 -> no tcgen05)
//   h = x @ W_enc + b_enc  -> mma.sync bf16 hi/lo-split GEMM (3-term, fp32 acc)
//   4 cross layers: s = x_l . w_l ; x_l += x0*s + b_l  -> warp-per-row kernel
// ---------------------------------------------------------------------------

#define BDIM 1024
#define HDIM 1024
#define KDIM 1024
#define DEPTH 4

// Scratch (no cudaMalloc allowed)
__device__ float          g_h[BDIM * HDIM];
__device__ __nv_bfloat16  g_xhi[BDIM * KDIM];
__device__ __nv_bfloat16  g_xlo[BDIM * KDIM];
__device__ __nv_bfloat16  g_wthi[HDIM * KDIM];   // W transposed: [n][k]
__device__ __nv_bfloat16  g_wtlo[HDIM * KDIM];

// ---------------------------------------------------------------------------
// helpers
// ---------------------------------------------------------------------------
__device__ __forceinline__ uint32_t smem_u32(const void* p) {
    uint32_t a;
    asm("{ .reg .u64 t; cvta.to.shared.u64 t, %1; cvt.u32.u64 %0, t; }"
        : "=r"(a) : "l"(p));
    return a;
}

__device__ __forceinline__ uint32_t swz(uint32_t off) {
    return off ^ ((off >> 3) & 0x70);   // SW128: granule ^= row&7
}

__device__ __forceinline__ void cp_async16(uint32_t smem_addr, const void* gptr) {
    asm volatile("cp.async.cg.shared.global [%0], [%1], 16;"
                 :: "r"(smem_addr), "l"(gptr));
}

__device__ __forceinline__ void ldsm_x4(uint32_t* r, uint32_t addr) {
    asm volatile("ldmatrix.sync.aligned.m8n8.x4.shared.b16 {%0,%1,%2,%3}, [%4];"
                 : "=r"(r[0]), "=r"(r[1]), "=r"(r[2]), "=r"(r[3]) : "r"(addr));
}

__device__ __forceinline__ void mma_bf16(float* d, const uint32_t* a, const uint32_t* b) {
    asm volatile(
        "mma.sync.aligned.m16n8k16.row.col.f32.bf16.bf16.f32 "
        "{%0,%1,%2,%3}, {%4,%5,%6,%7}, {%8,%9}, {%0,%1,%2,%3};"
        : "+f"(d[0]), "+f"(d[1]), "+f"(d[2]), "+f"(d[3])
        : "r"(a[0]), "r"(a[1]), "r"(a[2]), "r"(a[3]), "r"(b[0]), "r"(b[1]));
}

// ---------------------------------------------------------------------------
// Kernel: convert x (fp32 row-major [B,K]) -> hi/lo bf16
// ---------------------------------------------------------------------------
__global__ __launch_bounds__(256, 1) void convert_x_kernel(const float* __restrict__ x)
{
    int i = (blockIdx.x * 256 + threadIdx.x) * 4;
    float4 v = *(const float4*)(x + i);
    __nv_bfloat16 h0 = __float2bfloat16(v.x);
    __nv_bfloat16 h1 = __float2bfloat16(v.y);
    __nv_bfloat16 h2 = __float2bfloat16(v.z);
    __nv_bfloat16 h3 = __float2bfloat16(v.w);
    __nv_bfloat16 l0 = __float2bfloat16(v.x - __bfloat162float(h0));
    __nv_bfloat16 l1 = __float2bfloat16(v.y - __bfloat162float(h1));
    __nv_bfloat16 l2 = __float2bfloat16(v.z - __bfloat162float(h2));
    __nv_bfloat16 l3 = __float2bfloat16(v.w - __bfloat162float(h3));
    __nv_bfloat162* ph = (__nv_bfloat162*)(g_xhi + i);
    __nv_bfloat162* pl = (__nv_bfloat162*)(g_xlo + i);
    ph[0] = __nv_bfloat162(h0, h1);
    ph[1] = __nv_bfloat162(h2, h3);
    pl[0] = __nv_bfloat162(l0, l1);
    pl[1] = __nv_bfloat162(l2, l3);
}

// ---------------------------------------------------------------------------
// Kernel: convert + transpose W_enc (fp32 [K,N]) -> g_wt{hi,lo} bf16 [N,K]
// ---------------------------------------------------------------------------
__global__ __launch_bounds__(256, 1) void convert_wt_kernel(const float* __restrict__ W)
{
    __shared__ float tile[32][33];
    const int bx = blockIdx.x;   // n tile
    const int by = blockIdx.y;   // k tile
    const int tx = threadIdx.x;  // 0..31
    const int ty = threadIdx.y;  // 0..7

#pragma unroll
    for (int j = 0; j < 4; j++) {
        int k = by * 32 + ty + 8 * j;
        tile[ty + 8 * j][tx] = W[(size_t)k * HDIM + bx * 32 + tx];
    }
    __syncthreads();
#pragma unroll
    for (int j = 0; j < 4; j++) {
        float v = tile[tx][ty + 8 * j];
        int n = bx * 32 + ty + 8 * j;
        int k = by * 32 + tx;
        __nv_bfloat16 h = __float2bfloat16(v);
        g_wthi[(size_t)n * KDIM + k] = h;
        g_wtlo[(size_t)n * KDIM + k] = __float2bfloat16(v - __bfloat162float(h));
    }
}

// ---------------------------------------------------------------------------
// mma.sync GEMM: h = x @ W_enc + bias (bf16-split: hi*hi + hi*lo + lo*hi)
// CTA tile: BM=128 (x rows), BN=64 (W^T rows), BK=64. Grid (16, 8) = 128 CTAs.
// 8 warps, layout 4(M) x 2(N); warp tile 32x32 (2 m16-tiles x 4 n8-tiles).
// SMEM: 128B rows, SW128 XOR swizzle, double-buffered cp.async.
// ---------------------------------------------------------------------------
#define GBM 128
#define GBN 64
#define GKC 64
#define NCHUNK (KDIM / GKC)     // 16

#define SUB_AH 0
#define SUB_AL 16384
#define SUB_BH 32768
#define SUB_BL 40960
#define STAGE_BYTES 49152
#define GEMM_SMEM (2 * STAGE_BYTES)   // 98304

// load one stage (chunk c) into buffer `dst` (byte ptr)
__device__ __forceinline__ void load_stage(char* dst, uint32_t dstu,
                                           int bm, int bn, int c, int tid)
{
    const size_t koff = (size_t)c * GKC;
    // A hi/lo: 128 rows x 8 granules of 16B
#pragma unroll
    for (int it = 0; it < 4; ++it) {
        int idx = tid + it * 256;
        int row = idx >> 3;
        int g   = idx & 7;
        uint32_t so = swz(row * 128 + g * 16);
        const char* sa = (const char*)(g_xhi + (size_t)(bm * GBM + row) * KDIM + koff) + g * 16;
        cp_async16(dstu + SUB_AH + so, sa);
        const char* sl = (const char*)(g_xlo + (size_t)(bm * GBM + row) * KDIM + koff) + g * 16;
        cp_async16(dstu + SUB_AL + so, sl);
    }
    // B hi/lo: 64 rows x 8 granules
#pragma unroll
    for (int it = 0; it < 2; ++it) {
        int idx = tid + it * 256;
        int row = idx >> 3;
        int g   = idx & 7;
        uint32_t so = swz(row * 128 + g * 16);
        const char* sb = (const char*)(g_wthi + (size_t)(bn * GBN + row) * KDIM + koff) + g * 16;
        cp_async16(dstu + SUB_BH + so, sb);
        const char* sl = (const char*)(g_wtlo + (size_t)(bn * GBN + row) * KDIM + koff) + g * 16;
        cp_async16(dstu + SUB_BL + so, sl);
    }
    (void)dst;
}

__global__ __launch_bounds__(256, 1) void gemm_mma_kernel(const float* __restrict__ bias)
{
    extern __shared__ char smem[];
    const int tid  = threadIdx.x;
    const int wid  = tid >> 5;
    const int lane = tid & 31;
    const int bn   = blockIdx.x;   // 0..15
    const int bm   = blockIdx.y;   // 0..7
    const uint32_t sb = smem_u32(smem);

    const int warp_m = wid >> 1;   // 0..3 -> M offset 32*warp_m
    const int warp_n = wid & 1;    // 0..1 -> N offset 32*warp_n

    float acc[2][4][4];
#pragma unroll
    for (int mi = 0; mi < 2; mi++)
#pragma unroll
        for (int ni = 0; ni < 4; ni++)
#pragma unroll
            for (int j = 0; j < 4; j++) acc[mi][ni][j] = 0.0f;

    // ldmatrix per-lane address offsets (within a tile buffer, before adding
    // tile-row / k-step bases)
    // A x4 (m16 x k16): row = mbase + (lane&15), kb = kk*32 + (lane>>4)*16
    const int a_row_l = lane & 15;
    const int a_kb_l  = (lane >> 4) << 4;
    // B x4 (two n8 tiles x k16): n = nbase + (lane&7) + ((lane>>4)<<3),
    //                            kb = kk*32 + (((lane>>3)&1)<<4)
    const int b_row_l = (lane & 7) + ((lane >> 4) << 3);
    const int b_kb_l  = ((lane >> 3) & 1) << 4;

    // preload chunk 0
    load_stage(smem, sb, bm, bn, 0, tid);
    asm volatile("cp.async.commit_group;" ::: "memory");

    for (int c = 0; c < NCHUNK; ++c) {
        if (c + 1 < NCHUNK) {
            load_stage(smem + ((c + 1) & 1) * STAGE_BYTES,
                       sb + ((c + 1) & 1) * STAGE_BYTES, bm, bn, c + 1, tid);
            asm volatile("cp.async.commit_group;" ::: "memory");
            asm volatile("cp.async.wait_group 1;" ::: "memory");
        } else {
            asm volatile("cp.async.wait_group 0;" ::: "memory");
        }
        __syncthreads();

        const uint32_t base = sb + (c & 1) * STAGE_BYTES;
#pragma unroll
        for (int kk = 0; kk < 4; kk++) {
            uint32_t RAh[2][4], RAl[2][4], RBh[8], RBl[8];
#pragma unroll
            for (int mi = 0; mi < 2; mi++) {
                int row = warp_m * 32 + mi * 16 + a_row_l;
                uint32_t off = swz(row * 128 + kk * 32 + a_kb_l);
                ldsm_x4(RAh[mi], base + SUB_AH + off);
                ldsm_x4(RAl[mi], base + SUB_AL + off);
            }
#pragma unroll
            for (int p = 0; p < 2; p++) {   // n8-tile pairs
                int row = warp_n * 32 + p * 16 + b_row_l;
                uint32_t off = swz(row * 128 + kk * 32 + b_kb_l);
                ldsm_x4(&RBh[4 * p], base + SUB_BH + off);
                ldsm_x4(&RBl[4 * p], base + SUB_BL + off);
            }
#pragma unroll
            for (int mi = 0; mi < 2; mi++)
#pragma unroll
                for (int ni = 0; ni < 4; ni++) {
                    mma_bf16(acc[mi][ni], RAh[mi], &RBh[2 * ni]);   // hi*hi
                    mma_bf16(acc[mi][ni], RAh[mi], &RBl[2 * ni]);   // hi*lo
                    mma_bf16(acc[mi][ni], RAl[mi], &RBh[2 * ni]);   // lo*hi
                }
        }
        __syncthreads();
    }

    // epilogue: acc -> g_h (+bias)
    const int g = lane >> 2;
    const int t = lane & 3;
#pragma unroll
    for (int mi = 0; mi < 2; mi++) {
        int row0 = bm * GBM + warp_m * 32 + mi * 16 + g;
#pragma unroll
        for (int ni = 0; ni < 4; ni++) {
            int col = bn * GBN + warp_n * 32 + ni * 8 + t * 2;
            float b0 = __ldg(bias + col);
            float b1 = __ldg(bias + col + 1);
            float2 v0 = make_float2(acc[mi][ni][0] + b0, acc[mi][ni][1] + b1);
            float2 v1 = make_float2(acc[mi][ni][2] + b0, acc[mi][ni][3] + b1);
            *(float2*)(g_h + (size_t)row0 * HDIM + col) = v0;
            *(float2*)(g_h + (size_t)(row0 + 8) * HDIM + col) = v1;
        }
    }
}

// ---------------------------------------------------------------------------
// Fused CrossNet: one WARP per row (no __syncthreads), 32 floats/lane.
// ---------------------------------------------------------------------------
__global__ __launch_bounds__(256, 1) void cross_kernel(
    const float* __restrict__ ws, const float* __restrict__ bs,
    float* __restrict__ out)
{
    const int row = blockIdx.x * 8 + (threadIdx.x >> 5);
    const int lane = threadIdx.x & 31;

    const float4* hp = (const float4*)(g_h + (size_t)row * HDIM);
    float4 x0[8], xl[8];
#pragma unroll
    for (int i = 0; i < 8; i++) { x0[i] = hp[lane + 32 * i]; xl[i] = x0[i]; }

#pragma unroll
    for (int l = 0; l < DEPTH; l++) {
        const float4* wp = (const float4*)(ws + l * HDIM);
        float part = 0.0f;
#pragma unroll
        for (int i = 0; i < 8; i++) {
            float4 w = wp[lane + 32 * i];
            part += xl[i].x * w.x + xl[i].y * w.y + xl[i].z * w.z + xl[i].w * w.w;
        }
#pragma unroll
        for (int o = 16; o > 0; o >>= 1)
            part += __shfl_xor_sync(0xffffffffu, part, o);
        const float s = part;
        const float4* bp = (const float4*)(bs + l * HDIM);
#pragma unroll
        for (int i = 0; i < 8; i++) {
            float4 b = bp[lane + 32 * i];
            xl[i].x = fmaf(x0[i].x, s, xl[i].x) + b.x;
            xl[i].y = fmaf(x0[i].y, s, xl[i].y) + b.y;
            xl[i].z = fmaf(x0[i].z, s, xl[i].z) + b.z;
            xl[i].w = fmaf(x0[i].w, s, xl[i].w) + b.w;
        }
    }

    float4* op = (float4*)(out + (size_t)row * HDIM);
#pragma unroll
    for (int i = 0; i < 8; i++) op[lane + 32 * i] = xl[i];
}

// ---------------------------------------------------------------------------
extern "C" void kernel_launch(void* const* d_in, const int* in_sizes, int n_in,
                              void* d_out, int out_size)
{
    const float* x     = (const float*)d_in[0];
    const float* W_enc = (const float*)d_in[1];
    const float* b_enc = (const float*)d_in[2];
    const float* ws    = (const float*)d_in[3];
    const float* bs    = (const float*)d_in[4];
    float* out = (float*)d_out;

    cudaFuncSetAttribute(gemm_mma_kernel,
                         cudaFuncAttributeMaxDynamicSharedMemorySize, GEMM_SMEM);

    convert_x_kernel<<<BDIM * KDIM / (256 * 4), 256>>>(x);
    convert_wt_kernel<<<dim3(HDIM / 32, KDIM / 32), dim3(32, 8)>>>(W_enc);
    gemm_mma_kernel<<<dim3(HDIM / GBN, BDIM / GBM), 256, GEMM_SMEM>>>(b_enc);
    cross_kernel<<<BDIM / 8, 256>>>(ws, bs, out);
}

// round 4
// speedup vs baseline: 3.3709x; 1.0488x over previous
#include <cuda_runtime.h>
#include <cuda_bf16.h>
#include <cstdint>

// ---------------------------------------------------------------------------
// CrossNetLayer on GB300 (sm_103a; PTX target compute_103 -> no tcgen05)
//   h = x @ W_enc + b_enc  -> mma.sync bf16 hi/lo-split GEMM (3-term, fp32 acc)
//   4 cross layers: s = x_l . w_l ; x_l += x0*s + b_l  -> 4-warps-per-row
// ---------------------------------------------------------------------------

#define BDIM 1024
#define HDIM 1024
#define KDIM 1024
#define DEPTH 4

// Scratch (no cudaMalloc allowed)
__device__ float          g_h[BDIM * HDIM];
__device__ __nv_bfloat16  g_xhi[BDIM * KDIM];
__device__ __nv_bfloat16  g_xlo[BDIM * KDIM];
__device__ __nv_bfloat16  g_wthi[HDIM * KDIM];   // W transposed: [n][k]
__device__ __nv_bfloat16  g_wtlo[HDIM * KDIM];

// ---------------------------------------------------------------------------
// helpers
// ---------------------------------------------------------------------------
__device__ __forceinline__ uint32_t smem_u32(const void* p) {
    uint32_t a;
    asm("{ .reg .u64 t; cvta.to.shared.u64 t, %1; cvt.u32.u64 %0, t; }"
        : "=r"(a) : "l"(p));
    return a;
}

__device__ __forceinline__ uint32_t swz(uint32_t off) {
    return off ^ ((off >> 3) & 0x70);   // SW128: 16B granule ^= row&7
}

__device__ __forceinline__ void cp_async16(uint32_t smem_addr, const void* gptr) {
    asm volatile("cp.async.cg.shared.global [%0], [%1], 16;"
                 :: "r"(smem_addr), "l"(gptr));
}

__device__ __forceinline__ void ldsm_x4(uint32_t* r, uint32_t addr) {
    asm volatile("ldmatrix.sync.aligned.m8n8.x4.shared.b16 {%0,%1,%2,%3}, [%4];"
                 : "=r"(r[0]), "=r"(r[1]), "=r"(r[2]), "=r"(r[3]) : "r"(addr));
}

__device__ __forceinline__ void mma_bf16(float* d, const uint32_t* a, const uint32_t* b) {
    asm volatile(
        "mma.sync.aligned.m16n8k16.row.col.f32.bf16.bf16.f32 "
        "{%0,%1,%2,%3}, {%4,%5,%6,%7}, {%8,%9}, {%0,%1,%2,%3};"
        : "+f"(d[0]), "+f"(d[1]), "+f"(d[2]), "+f"(d[3])
        : "r"(a[0]), "r"(a[1]), "r"(a[2]), "r"(a[3]), "r"(b[0]), "r"(b[1]));
}

// ---------------------------------------------------------------------------
// Kernel: convert x (fp32 row-major [B,K]) -> hi/lo bf16
// ---------------------------------------------------------------------------
__global__ __launch_bounds__(256, 1) void convert_x_kernel(const float* __restrict__ x)
{
    int i = (blockIdx.x * 256 + threadIdx.x) * 4;
    float4 v = *(const float4*)(x + i);
    __nv_bfloat16 h0 = __float2bfloat16(v.x);
    __nv_bfloat16 h1 = __float2bfloat16(v.y);
    __nv_bfloat16 h2 = __float2bfloat16(v.z);
    __nv_bfloat16 h3 = __float2bfloat16(v.w);
    __nv_bfloat16 l0 = __float2bfloat16(v.x - __bfloat162float(h0));
    __nv_bfloat16 l1 = __float2bfloat16(v.y - __bfloat162float(h1));
    __nv_bfloat16 l2 = __float2bfloat16(v.z - __bfloat162float(h2));
    __nv_bfloat16 l3 = __float2bfloat16(v.w - __bfloat162float(h3));
    __nv_bfloat162* ph = (__nv_bfloat162*)(g_xhi + i);
    __nv_bfloat162* pl = (__nv_bfloat162*)(g_xlo + i);
    ph[0] = __nv_bfloat162(h0, h1);
    ph[1] = __nv_bfloat162(h2, h3);
    pl[0] = __nv_bfloat162(l0, l1);
    pl[1] = __nv_bfloat162(l2, l3);
}

// ---------------------------------------------------------------------------
// Kernel: convert + transpose W_enc (fp32 [K,N]) -> g_wt{hi,lo} bf16 [N,K]
// ---------------------------------------------------------------------------
__global__ __launch_bounds__(256, 1) void convert_wt_kernel(const float* __restrict__ W)
{
    __shared__ float tile[32][33];
    const int bx = blockIdx.x;   // n tile
    const int by = blockIdx.y;   // k tile
    const int tx = threadIdx.x;  // 0..31
    const int ty = threadIdx.y;  // 0..7

#pragma unroll
    for (int j = 0; j < 4; j++) {
        int k = by * 32 + ty + 8 * j;
        tile[ty + 8 * j][tx] = W[(size_t)k * HDIM + bx * 32 + tx];
    }
    __syncthreads();
#pragma unroll
    for (int j = 0; j < 4; j++) {
        float v = tile[tx][ty + 8 * j];
        int n = bx * 32 + ty + 8 * j;
        int k = by * 32 + tx;
        __nv_bfloat16 h = __float2bfloat16(v);
        g_wthi[(size_t)n * KDIM + k] = h;
        g_wtlo[(size_t)n * KDIM + k] = __float2bfloat16(v - __bfloat162float(h));
    }
}

// ---------------------------------------------------------------------------
// mma.sync GEMM: h = x @ W_enc + bias (bf16-split: hi*hi + hi*lo + lo*hi)
// CTA tile: BM=128, BN=64, BK=64. Grid (16, 8) = 128 CTAs (one full wave).
// 8 warps in 4(M) x 2(N); warp tile 32x32. SW128 swizzle, 3-stage cp.async.
// ---------------------------------------------------------------------------
#define GBM 128
#define GBN 64
#define GKC 64
#define NCHUNK (KDIM / GKC)     // 16

#define SUB_AH 0
#define SUB_AL 16384
#define SUB_BH 32768
#define SUB_BL 40960
#define STAGE_BYTES 49152
#define NSTAGE 3
#define GEMM_SMEM (NSTAGE * STAGE_BYTES)   // 147456

__global__ __launch_bounds__(256, 1) void gemm_mma_kernel(const float* __restrict__ bias)
{
    extern __shared__ char smem[];
    const int tid  = threadIdx.x;
    const int wid  = tid >> 5;
    const int lane = tid & 31;
    const int bn   = blockIdx.x;   // 0..15
    const int bm   = blockIdx.y;   // 0..7
    const uint32_t sb = smem_u32(smem);

    const int warp_m = wid >> 1;   // 0..3 -> M offset 32*warp_m
    const int warp_n = wid & 1;    // 0..1 -> N offset 32*warp_n

    // ---- precomputed load addressing (advance +128B per chunk) ----
    const char* pAh[4]; const char* pAl[4]; uint32_t offA[4];
#pragma unroll
    for (int it = 0; it < 4; ++it) {
        int idx = tid + it * 256;
        int row = idx >> 3;          // 0..127
        int g   = idx & 7;           // 16B granule
        size_t gb = ((size_t)(bm * GBM + row) * KDIM) * 2 + g * 16;
        pAh[it] = (const char*)g_xhi + gb;
        pAl[it] = (const char*)g_xlo + gb;
        offA[it] = swz(row * 128 + g * 16);
    }
    const char* pBh[2]; const char* pBl[2]; uint32_t offB[2];
#pragma unroll
    for (int it = 0; it < 2; ++it) {
        int idx = tid + it * 256;
        int row = idx >> 3;          // 0..63
        int g   = idx & 7;
        size_t gb = ((size_t)(bn * GBN + row) * KDIM) * 2 + g * 16;
        pBh[it] = (const char*)g_wthi + gb;
        pBl[it] = (const char*)g_wtlo + gb;
        offB[it] = swz(row * 128 + g * 16);
    }

    // ---- ldmatrix per-lane offset components ----
    const int a_row_l = lane & 15;
    const int a_kb_l  = (lane >> 4) << 4;
    const int b_row_l = (lane & 7) + ((lane >> 4) << 3);
    const int b_kb_l  = ((lane >> 3) & 1) << 4;

    float acc[2][4][4];
#pragma unroll
    for (int mi = 0; mi < 2; mi++)
#pragma unroll
        for (int ni = 0; ni < 4; ni++)
#pragma unroll
            for (int j = 0; j < 4; j++) acc[mi][ni][j] = 0.0f;

    // ---- prologue: preload chunks 0 and 1 ----
#pragma unroll
    for (int n = 0; n < 2; ++n) {
        uint32_t dst = sb + n * STAGE_BYTES;
        size_t go = (size_t)n * 128;
#pragma unroll
        for (int it = 0; it < 4; ++it) {
            cp_async16(dst + SUB_AH + offA[it], pAh[it] + go);
            cp_async16(dst + SUB_AL + offA[it], pAl[it] + go);
        }
#pragma unroll
        for (int it = 0; it < 2; ++it) {
            cp_async16(dst + SUB_BH + offB[it], pBh[it] + go);
            cp_async16(dst + SUB_BL + offB[it], pBl[it] + go);
        }
        asm volatile("cp.async.commit_group;" ::: "memory");
    }

    int stage = 0;     // = c % 3
    int nstage = 2;    // = (c+2) % 3
    for (int c = 0; c < NCHUNK; ++c) {
        if (c < NCHUNK - 1)
            asm volatile("cp.async.wait_group 1;" ::: "memory");
        else
            asm volatile("cp.async.wait_group 0;" ::: "memory");
        __syncthreads();

        // issue loads for chunk c+2 (buffer freed by the barrier above)
        if (c + 2 < NCHUNK) {
            uint32_t dst = sb + nstage * STAGE_BYTES;
            size_t go = (size_t)(c + 2) * 128;
#pragma unroll
            for (int it = 0; it < 4; ++it) {
                cp_async16(dst + SUB_AH + offA[it], pAh[it] + go);
                cp_async16(dst + SUB_AL + offA[it], pAl[it] + go);
            }
#pragma unroll
            for (int it = 0; it < 2; ++it) {
                cp_async16(dst + SUB_BH + offB[it], pBh[it] + go);
                cp_async16(dst + SUB_BL + offB[it], pBl[it] + go);
            }
            asm volatile("cp.async.commit_group;" ::: "memory");
        }

        // compute on chunk c
        const uint32_t base = sb + stage * STAGE_BYTES;
#pragma unroll
        for (int kk = 0; kk < 4; kk++) {
            uint32_t RAh[2][4], RAl[2][4], RBh[8], RBl[8];
#pragma unroll
            for (int mi = 0; mi < 2; mi++) {
                int row = warp_m * 32 + mi * 16 + a_row_l;
                uint32_t off = swz(row * 128 + kk * 32 + a_kb_l);
                ldsm_x4(RAh[mi], base + SUB_AH + off);
                ldsm_x4(RAl[mi], base + SUB_AL + off);
            }
#pragma unroll
            for (int p = 0; p < 2; p++) {
                int row = warp_n * 32 + p * 16 + b_row_l;
                uint32_t off = swz(row * 128 + kk * 32 + b_kb_l);
                ldsm_x4(&RBh[4 * p], base + SUB_BH + off);
                ldsm_x4(&RBl[4 * p], base + SUB_BL + off);
            }
#pragma unroll
            for (int mi = 0; mi < 2; mi++)
#pragma unroll
                for (int ni = 0; ni < 4; ni++) {
                    mma_bf16(acc[mi][ni], RAh[mi], &RBh[2 * ni]);   // hi*hi
                    mma_bf16(acc[mi][ni], RAh[mi], &RBl[2 * ni]);   // hi*lo
                    mma_bf16(acc[mi][ni], RAl[mi], &RBh[2 * ni]);   // lo*hi
                }
        }

        stage = (stage == 2) ? 0 : stage + 1;
        nstage = (nstage == 2) ? 0 : nstage + 1;
    }

    // epilogue: acc -> g_h (+bias)
    const int g = lane >> 2;
    const int t = lane & 3;
#pragma unroll
    for (int mi = 0; mi < 2; mi++) {
        int row0 = bm * GBM + warp_m * 32 + mi * 16 + g;
#pragma unroll
        for (int ni = 0; ni < 4; ni++) {
            int col = bn * GBN + warp_n * 32 + ni * 8 + t * 2;
            float b0 = __ldg(bias + col);
            float b1 = __ldg(bias + col + 1);
            float2 v0 = make_float2(acc[mi][ni][0] + b0, acc[mi][ni][1] + b1);
            float2 v1 = make_float2(acc[mi][ni][2] + b0, acc[mi][ni][3] + b1);
            *(float2*)(g_h + (size_t)row0 * HDIM + col) = v0;
            *(float2*)(g_h + (size_t)(row0 + 8) * HDIM + col) = v1;
        }
    }
}

// ---------------------------------------------------------------------------
// Fused CrossNet: 4 warps per row, 1024 blocks of 128 threads.
// Each lane holds 8 floats (2 float4). One __syncthreads per layer
// (double-buffered reduction slots remove the WAR barrier).
// ---------------------------------------------------------------------------
__global__ __launch_bounds__(128, 8) void cross_kernel(
    const float* __restrict__ ws, const float* __restrict__ bs,
    float* __restrict__ out)
{
    const int row  = blockIdx.x;
    const int tid  = threadIdx.x;     // 0..127
    const int wid  = tid >> 5;        // 0..3
    const int lane = tid & 31;

    __shared__ float red[2][4];

    const float4* hp = (const float4*)(g_h + (size_t)row * HDIM);
    float4 x0[2], xl[2];
#pragma unroll
    for (int i = 0; i < 2; i++) { x0[i] = hp[tid + 128 * i]; xl[i] = x0[i]; }

#pragma unroll
    for (int l = 0; l < DEPTH; l++) {
        const float4* wp = (const float4*)(ws + l * HDIM);
        float part = 0.0f;
#pragma unroll
        for (int i = 0; i < 2; i++) {
            float4 w = wp[tid + 128 * i];
            part += xl[i].x * w.x + xl[i].y * w.y + xl[i].z * w.z + xl[i].w * w.w;
        }
#pragma unroll
        for (int o = 16; o > 0; o >>= 1)
            part += __shfl_xor_sync(0xffffffffu, part, o);
        if (lane == 0) red[l & 1][wid] = part;
        __syncthreads();
        const float s = red[l & 1][0] + red[l & 1][1] +
                        red[l & 1][2] + red[l & 1][3];
        const float4* bp = (const float4*)(bs + l * HDIM);
#pragma unroll
        for (int i = 0; i < 2; i++) {
            float4 b = bp[tid + 128 * i];
            xl[i].x = fmaf(x0[i].x, s, xl[i].x) + b.x;
            xl[i].y = fmaf(x0[i].y, s, xl[i].y) + b.y;
            xl[i].z = fmaf(x0[i].z, s, xl[i].z) + b.z;
            xl[i].w = fmaf(x0[i].w, s, xl[i].w) + b.w;
        }
    }

    float4* op = (float4*)(out + (size_t)row * HDIM);
#pragma unroll
    for (int i = 0; i < 2; i++) op[tid + 128 * i] = xl[i];
}

// ---------------------------------------------------------------------------
extern "C" void kernel_launch(void* const* d_in, const int* in_sizes, int n_in,
                              void* d_out, int out_size)
{
    const float* x     = (const float*)d_in[0];
    const float* W_enc = (const float*)d_in[1];
    const float* b_enc = (const float*)d_in[2];
    const float* ws    = (const float*)d_in[3];
    const float* bs    = (const float*)d_in[4];
    float* out = (float*)d_out;

    cudaFuncSetAttribute(gemm_mma_kernel,
                         cudaFuncAttributeMaxDynamicSharedMemorySize, GEMM_SMEM);

    convert_x_kernel<<<BDIM * KDIM / (256 * 4), 256>>>(x);
    convert_wt_kernel<<<dim3(HDIM / 32, KDIM / 32), dim3(32, 8)>>>(W_enc);
    gemm_mma_kernel<<<dim3(HDIM / GBN, BDIM / GBM), 256, GEMM_SMEM>>>(b_enc);
    cross_kernel<<<BDIM, 128>>>(ws, bs, out);
}